// round 1
// baseline (speedup 1.0000x reference)
#include <cuda_runtime.h>
#include <math.h>

#define BB 4
#define CC 64
#define HH 128
#define WW 128
#define HWp (HH*WW)
#define OCA 27
#define KD 576            // C * 9

// scratch (no allocations allowed)
__device__ float g_xt[BB*HWp*CC];     // x in NHWC
__device__ float g_off[BB*OCA*HWp];   // offset conv output (mask channels already 2*sigmoid)
__device__ float g_wact[BB*CC*HWp];   // exp(sigmoid(align conv)) in NCHW

// ---------------------------------------------------------------------------
// Kernel 0: NCHW -> NHWC transpose of x
// ---------------------------------------------------------------------------
__global__ void k_transpose(const float* __restrict__ x) {
    __shared__ float tile[32][33];
    int b  = blockIdx.z;
    int c0 = blockIdx.y * 32;
    int p0 = blockIdx.x * 32;
    int tx = threadIdx.x, ty = threadIdx.y;
    #pragma unroll
    for (int i = ty; i < 32; i += 8)
        tile[i][tx] = x[(b*CC + c0 + i)*HWp + p0 + tx];
    __syncthreads();
    #pragma unroll
    for (int i = ty; i < 32; i += 8)
        g_xt[(b*HWp + p0 + i)*CC + c0 + tx] = tile[tx][i];
}

// ---------------------------------------------------------------------------
// Kernel A: 3x3 offset conv (64 -> 27), pad 1. Outputs g_off (NCHW).
// Channels 18..26 get the 2*sigmoid transform (mask), 0..17 stay raw (dy/dx).
// Per block: W_off resident in smem (576 x 28 padded). Tiles of 32 pixels
// along W; patch 3 x 34 x 64 in smem with stride-65 padding.
// 224 threads: t = tid%32 (pixel), g = tid/32 (oc group of 4).
// ---------------------------------------------------------------------------
#define A_THREADS 224
#define A_PS 65
#define A_SMEM_FLOATS (KD*28 + 3*34*A_PS)

__global__ __launch_bounds__(A_THREADS, 2)
void k_offconv(const float* __restrict__ w_off, const float* __restrict__ b_off) {
    extern __shared__ float sm[];
    float* Wo    = sm;            // [576][28]
    float* patch = sm + KD*28;    // [3][34][65]

    for (int i = threadIdx.x; i < KD*28; i += A_THREADS) {
        int j = i / 28, oc = i - j*28;
        float v = 0.f;
        if (oc < OCA) {
            int c = j / 9, tap = j - c*9;
            v = w_off[(oc*CC + c)*9 + tap];
        }
        Wo[i] = v;
    }
    __syncthreads();

    int t = threadIdx.x & 31;
    int g = threadIdx.x >> 5;          // 0..6
    const int ntiles = BB*HH*(WW/32);  // 2048

    for (int tile = blockIdx.x; tile < ntiles; tile += gridDim.x) {
        int w0 = (tile & 3) * 32;
        int h  = (tile >> 2) & (HH-1);
        int b  = tile >> 9;

        __syncthreads();   // previous tile's GEMM done before patch overwrite
        for (int i = threadIdx.x; i < 3*34*64; i += A_THREADS) {
            int c   = i & 63;
            int col = (i >> 6) % 34;
            int r   = i / (64*34);
            int row = h - 1 + r;
            int cc  = w0 - 1 + col;
            float v = 0.f;
            if ((unsigned)row < HH && (unsigned)cc < WW)
                v = g_xt[((size_t)b*HWp + row*WW + cc)*CC + c];
            patch[(r*34 + col)*A_PS + c] = v;
        }
        __syncthreads();

        float a0 = 0.f, a1 = 0.f, a2 = 0.f, a3 = 0.f;
        const float* Wg = Wo + 4*g;
        #pragma unroll 2
        for (int c = 0; c < 64; ++c) {
            #pragma unroll
            for (int tap = 0; tap < 9; ++tap) {
                int ty_ = tap / 3, tx_ = tap - ty_*3;
                float v = patch[(ty_*34 + t + tx_)*A_PS + c];
                float4 w4 = *(const float4*)(Wg + (c*9 + tap)*28);
                a0 = fmaf(v, w4.x, a0);
                a1 = fmaf(v, w4.y, a1);
                a2 = fmaf(v, w4.z, a2);
                a3 = fmaf(v, w4.w, a3);
            }
        }
        float accs[4] = {a0, a1, a2, a3};
        #pragma unroll
        for (int i = 0; i < 4; ++i) {
            int oc = 4*g + i;
            if (oc < OCA) {
                float val = accs[i] + b_off[oc];
                if (oc >= 18) val = 2.f / (1.f + expf(-val));   // mask = 2*sigmoid
                g_off[((b*OCA + oc)*HH + h)*WW + w0 + t] = val;
            }
        }
    }
}

// ---------------------------------------------------------------------------
// Kernel B: deformable sampling + 64x576 GEMM + exp(sigmoid), persistent.
// smem: W_align [576][64] (144KB) + s [32][577] (72KB) + meta + bias ~225KB.
// 512 threads. Sampling: (c = tid&63, q = tid>>6). GEMM: lane t = tid&31,
// group g = tid>>5 (16 groups of 4 oc): per K-step one broadcast LDS.128 of W
// + one conflict-free LDS.32 of s + 4 FFMA.
// ---------------------------------------------------------------------------
#define B_THREADS 512
#define S_STRIDE 577
#define B_SMEM_FLOATS (KD*64 + 32*S_STRIDE + 3*288 + 64)

__global__ __launch_bounds__(B_THREADS, 1)
void k_deform(const float* __restrict__ w_align, const float* __restrict__ b_align) {
    extern __shared__ float sm[];
    float* Ws  = sm;                      // [576][64], j = k*64 + c
    float* s   = Ws + KD*64;              // [32][577]
    float* mys = s + 32*S_STRIDE;         // [288] = [9][32]
    float* mxs = mys + 288;
    float* mm  = mxs + 288;
    float* bsm = mm + 288;                // [64]

    for (int i = threadIdx.x; i < KD*64; i += B_THREADS) {
        int oc = i & 63, j = i >> 6;
        int c = j & 63, k = j >> 6;
        Ws[i] = w_align[(oc*CC + c)*9 + k];
    }
    if (threadIdx.x < 64) bsm[threadIdx.x] = b_align[threadIdx.x];
    __syncthreads();

    int lane_t = threadIdx.x & 31;
    int g      = threadIdx.x >> 5;   // 0..15
    int cch    = threadIdx.x & 63;
    int q      = threadIdx.x >> 6;   // 0..7
    const int ntiles = BB*HH*(WW/32);  // 2048

    for (int tile = blockIdx.x; tile < ntiles; tile += gridDim.x) {
        int w0 = (tile & 3) * 32;
        int h  = (tile >> 2) & (HH-1);
        int b  = tile >> 9;

        __syncthreads();   // previous tile fully consumed
        for (int i = threadIdx.x; i < 288; i += B_THREADS) {
            int k = i >> 5, t = i & 31;
            const float* offb = g_off + ((size_t)b*OCA*HWp) + (size_t)h*WW + w0 + t;
            float dy = offb[(2*k    )*HWp];
            float dx = offb[(2*k + 1)*HWp];
            float m  = offb[(18 + k )*HWp];
            mys[i] = (float)(h  + (k/3) - 1) + dy;
            mxs[i] = (float)(w0 + t + (k%3) - 1) + dx;
            mm[i]  = m;
        }
        __syncthreads();

        // bilinear gather: 288 (k,t) pairs x 64 channels
        const float* xb = g_xt + (size_t)b*HWp*CC;
        for (int i = q; i < 288; i += 8) {
            int k = i >> 5, t = i & 31;
            float Y = mys[i], X = mxs[i];
            float yf = floorf(Y), xf = floorf(X);
            int y0 = (int)yf, x0 = (int)xf;
            float fy = Y - yf, fx = X - xf;
            float w00 = (1.f-fy)*(1.f-fx), w01 = (1.f-fy)*fx;
            float w10 = fy*(1.f-fx),       w11 = fy*fx;
            bool y0v = ((unsigned)y0     < HH);
            bool y1v = ((unsigned)(y0+1) < HH);
            bool x0v = ((unsigned)x0     < WW);
            bool x1v = ((unsigned)(x0+1) < WW);
            float v = 0.f;
            if (y0v && x0v) v = fmaf(w00, xb[((size_t)y0*WW + x0    )*CC + cch], v);
            if (y0v && x1v) v = fmaf(w01, xb[((size_t)y0*WW + x0 + 1)*CC + cch], v);
            if (y1v && x0v) v = fmaf(w10, xb[((size_t)(y0+1)*WW + x0    )*CC + cch], v);
            if (y1v && x1v) v = fmaf(w11, xb[((size_t)(y0+1)*WW + x0 + 1)*CC + cch], v);
            s[t*S_STRIDE + (k<<6) + cch] = v * mm[i];
        }
        __syncthreads();

        // GEMM: out[oc, t] = sum_j s[t][j] * Ws[j][oc],  j over 576
        float acc0 = 0.f, acc1 = 0.f, acc2 = 0.f, acc3 = 0.f;
        const float* srow = s + lane_t*S_STRIDE;
        const float* Wp   = Ws + (g << 2);
        #pragma unroll 4
        for (int j = 0; j < KD; ++j) {
            float sv = srow[j];
            float4 w4 = *(const float4*)(Wp + (j << 6));
            acc0 = fmaf(sv, w4.x, acc0);
            acc1 = fmaf(sv, w4.y, acc1);
            acc2 = fmaf(sv, w4.z, acc2);
            acc3 = fmaf(sv, w4.w, acc3);
        }
        int oc0 = g << 2;
        float accs[4] = {acc0, acc1, acc2, acc3};
        #pragma unroll
        for (int i = 0; i < 4; ++i) {
            float wv = accs[i] + bsm[oc0 + i];
            float sg = 1.f / (1.f + expf(-wv));
            g_wact[((b*CC + oc0 + i)*HH + h)*WW + w0 + lane_t] = expf(sg);
        }
    }
}

// ---------------------------------------------------------------------------
// Kernel C: out = pool3s2(wact*x) / pool3s2(wact), output (4,64,64,64)
// ---------------------------------------------------------------------------
__global__ void k_pool(const float* __restrict__ x, float* __restrict__ out) {
    int idx = blockIdx.x * 256 + threadIdx.x;
    if (idx >= BB*CC*64*64) return;
    int ow = idx & 63;
    int oh = (idx >> 6) & 63;
    int c  = (idx >> 12) & 63;
    int b  = idx >> 18;
    const float* wp = g_wact + ((size_t)b*CC + c)*HWp;
    const float* xp = x      + ((size_t)b*CC + c)*HWp;
    float num = 0.f, den = 0.f;
    int r0 = 2*oh - 1, c0 = 2*ow - 1;
    #pragma unroll
    for (int dr = 0; dr < 3; ++dr) {
        int r = r0 + dr;
        if ((unsigned)r >= HH) continue;
        #pragma unroll
        for (int dc = 0; dc < 3; ++dc) {
            int cl = c0 + dc;
            if ((unsigned)cl >= WW) continue;
            float wv = wp[r*WW + cl];
            num = fmaf(wv, xp[r*WW + cl], num);
            den += wv;
        }
    }
    out[idx] = num / den;
}

// ---------------------------------------------------------------------------
extern "C" void kernel_launch(void* const* d_in, const int* in_sizes, int n_in,
                              void* d_out, int out_size) {
    const float* x       = (const float*)d_in[0];
    const float* w_off   = (const float*)d_in[1];
    const float* b_off   = (const float*)d_in[2];
    const float* w_align = (const float*)d_in[3];
    const float* b_align = (const float*)d_in[4];
    float* out = (float*)d_out;

    (void)in_sizes; (void)n_in; (void)out_size;

    static_assert(A_SMEM_FLOATS*4 < 232000, "A smem");
    static_assert(B_SMEM_FLOATS*4 < 232000, "B smem");

    cudaFuncSetAttribute(k_offconv, cudaFuncAttributeMaxDynamicSharedMemorySize,
                         A_SMEM_FLOATS * 4);
    cudaFuncSetAttribute(k_deform, cudaFuncAttributeMaxDynamicSharedMemorySize,
                         B_SMEM_FLOATS * 4);

    dim3 tg(HWp/32, CC/32, BB);
    k_transpose<<<tg, dim3(32, 8)>>>(x);

    k_offconv<<<296, A_THREADS, A_SMEM_FLOATS * 4>>>(w_off, b_off);

    k_deform<<<148, B_THREADS, B_SMEM_FLOATS * 4>>>(w_align, b_align);

    k_pool<<<(BB*CC*64*64 + 255)/256, 256>>>(x, out);
}

// round 2
// speedup vs baseline: 1.1006x; 1.1006x over previous
#include <cuda_runtime.h>
#include <math.h>
#include <cstdint>

#define BB 4
#define CC 64
#define HH 128
#define WW 128
#define HWp (HH*WW)
#define OCA 27
#define KD 576            // C * 9

// scratch (no allocations allowed)
__device__ float g_xt[BB*HWp*CC];     // x in NHWC
__device__ float g_off[BB*OCA*HWp];   // offset conv output (mask channels already 2*sigmoid)
__device__ float g_wact[BB*CC*HWp];   // exp(sigmoid(align conv)) in NCHW

// ---- packed f32x2 helpers -------------------------------------------------
__device__ __forceinline__ uint64_t pack2(float v) {
    uint64_t r; asm("mov.b64 %0, {%1, %1};" : "=l"(r) : "f"(v)); return r;
}
__device__ __forceinline__ float2 unpack2(uint64_t p) {
    float2 f; asm("mov.b64 {%0, %1}, %2;" : "=f"(f.x), "=f"(f.y) : "l"(p)); return f;
}
#define FMA2(d, a, b) asm("fma.rn.f32x2 %0, %1, %2, %0;" : "+l"(d) : "l"(a), "l"(b))

__device__ __forceinline__ float fast_sigmoid(float v) {
    return __fdividef(1.f, 1.f + __expf(-v));
}

// ---------------------------------------------------------------------------
// Kernel 0: NCHW -> NHWC transpose of x
// ---------------------------------------------------------------------------
__global__ void k_transpose(const float* __restrict__ x) {
    __shared__ float tile[32][33];
    int b  = blockIdx.z;
    int c0 = blockIdx.y * 32;
    int p0 = blockIdx.x * 32;
    int tx = threadIdx.x, ty = threadIdx.y;
    #pragma unroll
    for (int i = ty; i < 32; i += 8)
        tile[i][tx] = x[(b*CC + c0 + i)*HWp + p0 + tx];
    __syncthreads();
    #pragma unroll
    for (int i = ty; i < 32; i += 8)
        g_xt[(b*HWp + p0 + i)*CC + c0 + tx] = tile[tx][i];
}

// ---------------------------------------------------------------------------
// Kernel A: 3x3 offset conv (64 -> 27 padded to 32), pad 1. Outputs g_off.
// 256 threads = 8 warps: oc-octet o=wid&3 (8 oc), K-half kh=wid>>2 (32 ch).
// Per j-step: 1 LDS.32 + 1 pack + 2 LDS.128 + 4 FFMA2 (=8 lane-FMA-pairs).
// kh=1 partials reduced through the (dead) patch buffer.
// ---------------------------------------------------------------------------
#define A_THREADS 256
#define A_PS 65
#define A_SMEM_FLOATS (KD*32 + 3*34*A_PS)

__global__ __launch_bounds__(A_THREADS, 2)
void k_offconv(const float* __restrict__ w_off, const float* __restrict__ b_off) {
    extern __shared__ float sm[];
    float* Wo    = sm;            // [576][32]  j = c*9+tap
    float* patch = sm + KD*32;    // [3][34][65], also reused as reduction scratch

    for (int i = threadIdx.x; i < KD*32; i += A_THREADS) {
        int j = i >> 5, oc = i & 31;
        float v = 0.f;
        if (oc < OCA) {
            int c = j / 9, tap = j - c*9;
            v = w_off[(oc*CC + c)*9 + tap];
        }
        Wo[i] = v;
    }
    __syncthreads();

    int t   = threadIdx.x & 31;
    int wid = threadIdx.x >> 5;
    int o   = wid & 3;            // oc octet
    int kh  = wid >> 2;           // K half (channels)
    int oc0 = o * 8;
    int c0  = kh * 32;
    const int ntiles = BB*HH*(WW/32);  // 2048

    for (int tile = blockIdx.x; tile < ntiles; tile += gridDim.x) {
        int w0 = (tile & 3) * 32;
        int h  = (tile >> 2) & (HH-1);
        int b  = tile >> 9;

        __syncthreads();   // previous tile fully done before patch overwrite
        for (int i = threadIdx.x; i < 3*34*64; i += A_THREADS) {
            int c   = i & 63;
            int col = (i >> 6) % 34;
            int r   = i / (64*34);
            int row = h - 1 + r;
            int cc  = w0 - 1 + col;
            float v = 0.f;
            if ((unsigned)row < HH && (unsigned)cc < WW)
                v = g_xt[((size_t)b*HWp + row*WW + cc)*CC + c];
            patch[(r*34 + col)*A_PS + c] = v;
        }
        __syncthreads();

        uint64_t acc[4] = {0, 0, 0, 0};
        #pragma unroll 2
        for (int ci = 0; ci < 32; ++ci) {
            int c = c0 + ci;
            #pragma unroll
            for (int tap = 0; tap < 9; ++tap) {
                int ty_ = tap / 3, tx_ = tap - ty_*3;
                uint64_t sv2 = pack2(patch[(ty_*34 + t + tx_)*A_PS + c]);
                const float* wrow = Wo + (((c*9 + tap) << 5) + oc0);
                ulonglong2 wa = *(const ulonglong2*)(wrow);
                ulonglong2 wb = *(const ulonglong2*)(wrow + 4);
                FMA2(acc[0], sv2, wa.x);
                FMA2(acc[1], sv2, wa.y);
                FMA2(acc[2], sv2, wb.x);
                FMA2(acc[3], sv2, wb.y);
            }
        }
        __syncthreads();   // GEMM reads of patch done -> reuse as scratch

        float* red = patch;  // [32 oc][32 t]
        if (kh == 1) {
            #pragma unroll
            for (int i = 0; i < 4; ++i) {
                float2 f = unpack2(acc[i]);
                red[(oc0 + 2*i    )*32 + t] = f.x;
                red[(oc0 + 2*i + 1)*32 + t] = f.y;
            }
        }
        __syncthreads();
        if (kh == 0) {
            #pragma unroll
            for (int i = 0; i < 4; ++i) {
                float2 f = unpack2(acc[i]);
                float vals[2] = {f.x, f.y};
                #pragma unroll
                for (int s2 = 0; s2 < 2; ++s2) {
                    int oc = oc0 + 2*i + s2;
                    if (oc < OCA) {
                        float val = vals[s2] + red[oc*32 + t] + b_off[oc];
                        if (oc >= 18) val = 2.f * fast_sigmoid(val);
                        g_off[((b*OCA + oc)*HH + h)*WW + w0 + t] = val;
                    }
                }
            }
        }
    }
}

// ---------------------------------------------------------------------------
// Kernel B: deformable sampling + 64x576 GEMM + exp(sigmoid), persistent.
// smem: W_align [576][64] (144KB) + s [32][577] (72KB) + meta + bias ~225KB.
// GEMM: 16 warps = 4 oc-groups(16 oc) x 4 K-splits(144 j). Per j-step:
// 1 LDS.32 + 1 pack + 4 LDS.128 + 8 FFMA2 (=16 lane-FMA-pairs) -> FFMA2-bound.
// K-split partials reduced through the (dead) s buffer.
// ---------------------------------------------------------------------------
#define B_THREADS 512
#define S_STRIDE 577
#define B_SMEM_FLOATS (KD*64 + 32*S_STRIDE + 3*288 + 64)

__global__ __launch_bounds__(B_THREADS, 1)
void k_deform(const float* __restrict__ w_align, const float* __restrict__ b_align) {
    extern __shared__ float sm[];
    float* Ws  = sm;                      // [576][64], j = k*64 + c
    float* s   = Ws + KD*64;              // [32][577], reused as reduction scratch
    float* mys = s + 32*S_STRIDE;         // [288] = [9][32]
    float* mxs = mys + 288;
    float* mm  = mxs + 288;
    float* bsm = mm + 288;                // [64]

    for (int i = threadIdx.x; i < KD*64; i += B_THREADS) {
        int oc = i & 63, j = i >> 6;
        int c = j & 63, k = j >> 6;
        Ws[i] = w_align[(oc*CC + c)*9 + k];
    }
    if (threadIdx.x < 64) bsm[threadIdx.x] = b_align[threadIdx.x];
    __syncthreads();

    int lane_t = threadIdx.x & 31;
    int wid    = threadIdx.x >> 5;
    int o      = wid & 3;            // oc group of 16
    int kq     = wid >> 2;           // K quarter
    int oc0    = o * 16;
    int j0     = kq * 144;
    int cch    = threadIdx.x & 63;
    int q      = threadIdx.x >> 6;   // 0..7
    const int ntiles = BB*HH*(WW/32);  // 2048

    for (int tile = blockIdx.x; tile < ntiles; tile += gridDim.x) {
        int w0 = (tile & 3) * 32;
        int h  = (tile >> 2) & (HH-1);
        int b  = tile >> 9;

        __syncthreads();   // previous tile fully consumed (incl. reduction reads)
        for (int i = threadIdx.x; i < 288; i += B_THREADS) {
            int k = i >> 5, t = i & 31;
            const float* offb = g_off + ((size_t)b*OCA*HWp) + (size_t)h*WW + w0 + t;
            float dy = offb[(2*k    )*HWp];
            float dx = offb[(2*k + 1)*HWp];
            float m  = offb[(18 + k )*HWp];
            mys[i] = (float)(h  + (k/3) - 1) + dy;
            mxs[i] = (float)(w0 + t + (k%3) - 1) + dx;
            mm[i]  = m;
        }
        __syncthreads();

        // bilinear gather: 288 (k,t) pairs x 64 channels
        const float* xb = g_xt + (size_t)b*HWp*CC;
        for (int i = q; i < 288; i += 8) {
            int k = i >> 5, t = i & 31;
            float Y = mys[i], X = mxs[i];
            float yf = floorf(Y), xf = floorf(X);
            int y0 = (int)yf, x0 = (int)xf;
            float fy = Y - yf, fx = X - xf;
            float w00 = (1.f-fy)*(1.f-fx), w01 = (1.f-fy)*fx;
            float w10 = fy*(1.f-fx),       w11 = fy*fx;
            bool y0v = ((unsigned)y0     < HH);
            bool y1v = ((unsigned)(y0+1) < HH);
            bool x0v = ((unsigned)x0     < WW);
            bool x1v = ((unsigned)(x0+1) < WW);
            float v = 0.f;
            if (y0v && x0v) v = fmaf(w00, xb[((size_t)y0*WW + x0    )*CC + cch], v);
            if (y0v && x1v) v = fmaf(w01, xb[((size_t)y0*WW + x0 + 1)*CC + cch], v);
            if (y1v && x0v) v = fmaf(w10, xb[((size_t)(y0+1)*WW + x0    )*CC + cch], v);
            if (y1v && x1v) v = fmaf(w11, xb[((size_t)(y0+1)*WW + x0 + 1)*CC + cch], v);
            s[t*S_STRIDE + (k<<6) + cch] = v * mm[i];
        }
        __syncthreads();

        // GEMM: out[oc, t] = sum_j s[t][j] * Ws[j][oc]
        uint64_t acc[8] = {0,0,0,0,0,0,0,0};
        {
            const float* srow  = s + lane_t*S_STRIDE + j0;
            const float* Wbase = Ws + ((j0 << 6) + oc0);
            #pragma unroll 4
            for (int j = 0; j < 144; ++j) {
                uint64_t sv2 = pack2(srow[j]);
                const float* wrow = Wbase + (j << 6);
                ulonglong2 wa = *(const ulonglong2*)(wrow);
                ulonglong2 wb = *(const ulonglong2*)(wrow + 4);
                ulonglong2 wc = *(const ulonglong2*)(wrow + 8);
                ulonglong2 wd = *(const ulonglong2*)(wrow + 12);
                FMA2(acc[0], sv2, wa.x);
                FMA2(acc[1], sv2, wa.y);
                FMA2(acc[2], sv2, wb.x);
                FMA2(acc[3], sv2, wb.y);
                FMA2(acc[4], sv2, wc.x);
                FMA2(acc[5], sv2, wc.y);
                FMA2(acc[6], sv2, wd.x);
                FMA2(acc[7], sv2, wd.y);
            }
        }
        __syncthreads();   // all GEMM reads of s done -> reuse as scratch

        float* red = s;    // [3][64 oc][32 t] for kq = 1..3
        if (kq > 0) {
            int base = (kq - 1) * 2048;
            #pragma unroll
            for (int i = 0; i < 8; ++i) {
                float2 f = unpack2(acc[i]);
                red[base + (oc0 + 2*i    )*32 + lane_t] = f.x;
                red[base + (oc0 + 2*i + 1)*32 + lane_t] = f.y;
            }
        }
        __syncthreads();
        if (kq == 0) {
            #pragma unroll
            for (int i = 0; i < 8; ++i) {
                float2 f = unpack2(acc[i]);
                float vals[2] = {f.x, f.y};
                #pragma unroll
                for (int s2 = 0; s2 < 2; ++s2) {
                    int oc = oc0 + 2*i + s2;
                    int ri = oc*32 + lane_t;
                    float wv = vals[s2] + red[ri] + red[2048 + ri] + red[4096 + ri]
                             + bsm[oc];
                    float sg = fast_sigmoid(wv);
                    g_wact[((b*CC + oc)*HH + h)*WW + w0 + lane_t] = __expf(sg);
                }
            }
        }
    }
}

// ---------------------------------------------------------------------------
// Kernel C: out = pool3s2(wact*x) / pool3s2(wact), output (4,64,64,64)
// ---------------------------------------------------------------------------
__global__ void k_pool(const float* __restrict__ x, float* __restrict__ out) {
    int idx = blockIdx.x * 256 + threadIdx.x;
    if (idx >= BB*CC*64*64) return;
    int ow = idx & 63;
    int oh = (idx >> 6) & 63;
    int c  = (idx >> 12) & 63;
    int b  = idx >> 18;
    const float* wp = g_wact + ((size_t)b*CC + c)*HWp;
    const float* xp = x      + ((size_t)b*CC + c)*HWp;
    float num = 0.f, den = 0.f;
    int r0 = 2*oh - 1, c0 = 2*ow - 1;
    #pragma unroll
    for (int dr = 0; dr < 3; ++dr) {
        int r = r0 + dr;
        if ((unsigned)r >= HH) continue;
        #pragma unroll
        for (int dc = 0; dc < 3; ++dc) {
            int cl = c0 + dc;
            if ((unsigned)cl >= WW) continue;
            float wv = wp[r*WW + cl];
            num = fmaf(wv, xp[r*WW + cl], num);
            den += wv;
        }
    }
    out[idx] = num / den;
}

// ---------------------------------------------------------------------------
extern "C" void kernel_launch(void* const* d_in, const int* in_sizes, int n_in,
                              void* d_out, int out_size) {
    const float* x       = (const float*)d_in[0];
    const float* w_off   = (const float*)d_in[1];
    const float* b_off   = (const float*)d_in[2];
    const float* w_align = (const float*)d_in[3];
    const float* b_align = (const float*)d_in[4];
    float* out = (float*)d_out;

    (void)in_sizes; (void)n_in; (void)out_size;

    static_assert(A_SMEM_FLOATS*4 < 113000, "A smem (2 CTAs/SM)");
    static_assert(B_SMEM_FLOATS*4 < 227000, "B smem");

    cudaFuncSetAttribute(k_offconv, cudaFuncAttributeMaxDynamicSharedMemorySize,
                         A_SMEM_FLOATS * 4);
    cudaFuncSetAttribute(k_deform, cudaFuncAttributeMaxDynamicSharedMemorySize,
                         B_SMEM_FLOATS * 4);

    dim3 tg(HWp/32, CC/32, BB);
    k_transpose<<<tg, dim3(32, 8)>>>(x);

    k_offconv<<<296, A_THREADS, A_SMEM_FLOATS * 4>>>(w_off, b_off);

    k_deform<<<148, B_THREADS, B_SMEM_FLOATS * 4>>>(w_align, b_align);

    k_pool<<<(BB*CC*64*64 + 255)/256, 256>>>(x, out);
}

// round 4
// speedup vs baseline: 3.0202x; 2.7440x over previous
#include <cuda_runtime.h>
#include <cstdint>
#include <math.h>

#define BB 4
#define CC 64
#define HH 128
#define WW 128
#define HWp (HH*WW)
#define OCA 27

// scratch (no allocations allowed)
__device__ float g_xt[BB*HWp*CC];     // x in NHWC
__device__ float g_off[BB*OCA*HWp];   // offset conv out (mask channels = 2*sigmoid)
__device__ float g_wact[BB*CC*HWp];   // exp(sigmoid(align conv)) NCHW

// ============================ helpers =======================================
__device__ __forceinline__ uint32_t s2u(const void* p) {
    uint32_t a;
    asm("{ .reg .u64 t; cvta.to.shared.u64 t, %1; cvt.u32.u64 %0, t; }" : "=r"(a) : "l"(p));
    return a;
}
__device__ __forceinline__ float to_tf32(float x) {
    uint32_t r;
    asm("cvt.rna.tf32.f32 %0, %1;" : "=r"(r) : "f"(x));
    return __uint_as_float(r);
}
#define LDSM_X4(a, addr) \
    asm volatile("ldmatrix.sync.aligned.m8n8.x4.shared.b16 {%0,%1,%2,%3}, [%4];" \
        : "=r"((a)[0]), "=r"((a)[1]), "=r"((a)[2]), "=r"((a)[3]) : "r"(addr))
#define MMA_TF32(d, a, b) \
    asm volatile("mma.sync.aligned.m16n8k8.row.col.f32.tf32.tf32.f32 " \
        "{%0,%1,%2,%3}, {%4,%5,%6,%7}, {%8,%9}, {%0,%1,%2,%3};" \
        : "+f"((d)[0]), "+f"((d)[1]), "+f"((d)[2]), "+f"((d)[3]) \
        : "r"((a)[0]), "r"((a)[1]), "r"((a)[2]), "r"((a)[3]), \
          "r"((b)[0]), "r"((b)[1]))

__device__ __forceinline__ float fast_sigmoid(float v) {
    return __fdividef(1.f, 1.f + __expf(-v));
}

// A-tile swizzle: [128 rows][16 chunks of 16B]; chunk ^= (row&7)
__device__ __forceinline__ uint32_t a_off(int row, int chunk) {
    return (uint32_t)(row*256 + (((chunk ^ (row & 7)) & 15) << 4));
}

// ---------------------------------------------------------------------------
// Kernel 0: NCHW -> NHWC transpose of x
// ---------------------------------------------------------------------------
__global__ void k_transpose(const float* __restrict__ x) {
    __shared__ float tile[32][33];
    int b  = blockIdx.z;
    int c0 = blockIdx.y * 32;
    int p0 = blockIdx.x * 32;
    int tx = threadIdx.x, ty = threadIdx.y;
    #pragma unroll
    for (int i = ty; i < 32; i += 8)
        tile[i][tx] = x[(b*CC + c0 + i)*HWp + p0 + tx];
    __syncthreads();
    #pragma unroll
    for (int i = ty; i < 32; i += 8)
        g_xt[(b*HWp + p0 + i)*CC + c0 + tx] = tile[tx][i];
}

// ===========================================================================
// Kernel A: 3x3 offset conv 64->27 via tf32 mma.sync. Tile = one row (128px).
// smem: WFRAG [72 kstep][4 ntile][64] fragment-ordered (73728B) + ABUF 32768B.
// 16 warps: wm = wid&3 (32px -> 2 mtiles), wn = wid>>2 (8 oc -> 1 ntile).
// ===========================================================================
#define A_WFRAG  0
#define A_ABUF   73728
#define A_SMEM   (A_ABUF + 32768)

__global__ __launch_bounds__(512, 1)
void k_offconv_mma(const float* __restrict__ w_off, const float* __restrict__ b_off) {
    extern __shared__ char smem[];
    uint32_t sb = s2u(smem);
    int tid = threadIdx.x;
    int wid = tid >> 5, lane = tid & 31;

    // WFRAG fill: [ks][nt][lane*2+half] = W[ks*8 + lane%4 + half*4][nt*8 + lane/4]
    for (int i = tid; i < 72*4*64; i += 512) {
        int half = i & 1, l = (i >> 1) & 31, nt = (i >> 6) & 3, ks = i >> 8;
        int k = ks*8 + (l & 3) + half*4;
        int n = nt*8 + (l >> 2);
        int tap = k >> 6, c = k & 63;
        float v = (n < OCA) ? to_tf32(w_off[(n*CC + c)*9 + tap]) : 0.f;
        ((float*)smem)[i] = v;
    }
    __syncthreads();

    int wm = wid & 3, wn = wid >> 2;
    // ldmatrix row/address pattern (per mtile)
    int lrow_in = (lane & 7) + ((lane >> 3) & 1) * 8;  // 0..15 within mtile
    int g4 = lane >> 4;                                 // chunk selector
    int q16 = tid & 15;                                 // channel quad (fill)
    const int ntiles = BB*HH;

    for (int tile = blockIdx.x; tile < ntiles; tile += gridDim.x) {
        int h = tile & (HH-1);
        int b = tile >> 7;
        const char* xbb = (const char*)(g_xt + (size_t)b*HWp*CC);

        float acc[2][8];
        #pragma unroll
        for (int mt = 0; mt < 2; ++mt)
            #pragma unroll
            for (int i = 0; i < 8; ++i) acc[mt][i] = 0.f;

        for (int tap = 0; tap < 9; ++tap) {
            __syncthreads();
            int row = h + (tap/3) - 1;
            int dxk = (tap % 3) - 1;
            // fill ABUF[px][ch] = x[row][px+dxk][ch] (tf32-rounded), swizzled
            #pragma unroll
            for (int j = 0; j < 4; ++j) {
                int it = tid + j*512;
                int px = it >> 4;
                int col = px + dxk;
                float4 v = make_float4(0.f, 0.f, 0.f, 0.f);
                if ((unsigned)row < HH && (unsigned)col < WW)
                    v = *(const float4*)(xbb + (((size_t)row*WW + col) << 8) + (q16 << 4));
                v.x = to_tf32(v.x); v.y = to_tf32(v.y);
                v.z = to_tf32(v.z); v.w = to_tf32(v.w);
                *(float4*)(smem + A_ABUF + a_off(px, q16)) = v;
            }
            __syncthreads();

            #pragma unroll
            for (int ks = 0; ks < 8; ++ks) {
                int gks = tap*8 + ks;
                uint32_t bfr[2];
                *(float2*)bfr = *(const float2*)(smem + A_WFRAG
                                 + (((gks*4 + wn)*64 + lane*2) << 2));
                #pragma unroll
                for (int mt = 0; mt < 2; ++mt) {
                    int row_a = wm*32 + mt*16 + lrow_in;
                    uint32_t addr = sb + A_ABUF + a_off(row_a, ks*2 + g4);
                    uint32_t a[4];
                    LDSM_X4(a, addr);
                    MMA_TF32(acc[mt] + 0, a, bfr);
                    // second half of the 8-oc tile handled by same B frag?  no:
                    // one ntile = 8 oc, exactly one mma per (mt,ks). acc[mt][0..3].
                }
                (void)0;
            }
        }
        // NOTE: acc[mt][4..7] unused in this layout (kept for symmetry)

        // epilogue: oc = wn*8 + (lane&3)*2 (+1); px = wm*32 + mt*16 + lane/4 (+8)
        int ocb = wn*8 + (lane & 3)*2;
        #pragma unroll
        for (int mt = 0; mt < 2; ++mt) {
            int px = wm*32 + mt*16 + (lane >> 2);
            #pragma unroll
            for (int dd = 0; dd < 4; ++dd) {
                int oc = ocb + (dd & 1);
                int pxx = px + (dd >> 1)*8;
                if (oc < OCA) {
                    float val = acc[mt][dd] + __ldg(b_off + oc);
                    if (oc >= 18) val = 2.f * fast_sigmoid(val);
                    g_off[((b*OCA + oc)*HH + h)*WW + pxx] = val;
                }
            }
        }
    }
}

// ===========================================================================
// Kernel B: deformable sampling + tf32 mma.sync + exp(sigmoid).
// smem: WFRAG [72][8][64] (147456B) + ABUF (32768B) + metaW (18432B) +
//       metaP (18432B) = 217088B.
// 16 warps: wm = wid&7 (16px -> 1 mtile), wn = wid>>3 (32oc -> 4 ntiles).
// ===========================================================================
#define B_WFRAG  0
#define B_ABUF   147456
#define B_METAW  (B_ABUF + 32768)    // float4[9*128]
#define B_METAP  (B_METAW + 18432)   // int4[9*128]
#define B_SMEM   (B_METAP + 18432)   // 217088

__global__ __launch_bounds__(512, 1)
void k_deform_mma(const float* __restrict__ w_align, const float* __restrict__ b_align) {
    extern __shared__ char smem[];
    uint32_t sb = s2u(smem);
    int tid = threadIdx.x;
    int wid = tid >> 5, lane = tid & 31;

    for (int i = tid; i < 72*8*64; i += 512) {
        int half = i & 1, l = (i >> 1) & 31, nt = (i >> 6) & 7, ks = i >> 9;
        int k = ks*8 + (l & 3) + half*4;
        int n = nt*8 + (l >> 2);
        int tap = k >> 6, c = k & 63;
        ((float*)smem)[i] = to_tf32(w_align[(n*CC + c)*9 + tap]);
    }
    __syncthreads();

    int wm = wid & 7, wn = wid >> 3;
    int lrow_in = (lane & 7) + ((lane >> 3) & 1) * 8;
    int g4 = lane >> 4;
    int q16 = tid & 15;
    float4* metaW = (float4*)(smem + B_METAW);
    int4*   metaP = (int4*)(smem + B_METAP);
    const int ntiles = BB*HH;

    for (int tile = blockIdx.x; tile < ntiles; tile += gridDim.x) {
        int h = tile & (HH-1);
        int b = tile >> 7;
        const char* xbb = (const char*)(g_xt + (size_t)b*HWp*CC);

        __syncthreads();   // prev tile's tap-8 mma reads of ABUF/meta done
        // precompute bilinear meta for 9 taps x 128 px
        for (int i = tid; i < 9*128; i += 512) {
            int tap = i >> 7, px = i & 127;
            const float* ob = g_off + (size_t)b*OCA*HWp + (size_t)h*WW + px;
            float dy = ob[(2*tap    )*HWp];
            float dx = ob[(2*tap + 1)*HWp];
            float m  = ob[(18 + tap )*HWp];
            float Y = (float)(h  + (tap/3) - 1) + dy;
            float X = (float)(px + (tap%3) - 1) + dx;
            float yf = floorf(Y), xf = floorf(X);
            int y0 = (int)yf, x0 = (int)xf;
            float fy = Y - yf, fx = X - xf;
            bool y0v = ((unsigned)y0     < HH);
            bool y1v = ((unsigned)(y0+1) < HH);
            bool x0v = ((unsigned)x0     < WW);
            bool x1v = ((unsigned)(x0+1) < WW);
            float4 w4;
            w4.x = (1.f-fy)*(1.f-fx) * m * (y0v && x0v);
            w4.y = (1.f-fy)*fx       * m * (y0v && x1v);
            w4.z = fy*(1.f-fx)       * m * (y1v && x0v);
            w4.w = fy*fx             * m * (y1v && x1v);
            int yc0 = min(max(y0, 0), HH-1), yc1 = min(max(y0+1, 0), HH-1);
            int xc0 = min(max(x0, 0), WW-1), xc1 = min(max(x0+1, 0), WW-1);
            int4 p4;
            p4.x = (yc0*WW + xc0) << 8;
            p4.y = (yc0*WW + xc1) << 8;
            p4.z = (yc1*WW + xc0) << 8;
            p4.w = (yc1*WW + xc1) << 8;
            metaW[i] = w4;
            metaP[i] = p4;
        }

        float acc[4][4];
        #pragma unroll
        for (int nt = 0; nt < 4; ++nt)
            #pragma unroll
            for (int i = 0; i < 4; ++i) acc[nt][i] = 0.f;

        for (int tap = 0; tap < 9; ++tap) {
            __syncthreads();   // meta visible / prev mma reads of ABUF done
            #pragma unroll
            for (int j = 0; j < 4; ++j) {
                int it = tid + j*512;
                int px = it >> 4;
                float4 w4 = metaW[tap*128 + px];
                int4   p4 = metaP[tap*128 + px];
                int qo = q16 << 4;
                float4 c00 = *(const float4*)(xbb + p4.x + qo);
                float4 c01 = *(const float4*)(xbb + p4.y + qo);
                float4 c10 = *(const float4*)(xbb + p4.z + qo);
                float4 c11 = *(const float4*)(xbb + p4.w + qo);
                float4 v;
                v.x = fmaf(w4.x,c00.x, fmaf(w4.y,c01.x, fmaf(w4.z,c10.x, w4.w*c11.x)));
                v.y = fmaf(w4.x,c00.y, fmaf(w4.y,c01.y, fmaf(w4.z,c10.y, w4.w*c11.y)));
                v.z = fmaf(w4.x,c00.z, fmaf(w4.y,c01.z, fmaf(w4.z,c10.z, w4.w*c11.z)));
                v.w = fmaf(w4.x,c00.w, fmaf(w4.y,c01.w, fmaf(w4.z,c10.w, w4.w*c11.w)));
                v.x = to_tf32(v.x); v.y = to_tf32(v.y);
                v.z = to_tf32(v.z); v.w = to_tf32(v.w);
                *(float4*)(smem + B_ABUF + a_off(px, q16)) = v;
            }
            __syncthreads();

            #pragma unroll
            for (int ks = 0; ks < 8; ++ks) {
                int gks = tap*8 + ks;
                int row_a = wm*16 + lrow_in;
                uint32_t addr = sb + B_ABUF + a_off(row_a, ks*2 + g4);
                uint32_t a[4];
                LDSM_X4(a, addr);
                #pragma unroll
                for (int nt = 0; nt < 4; ++nt) {
                    uint32_t bfr[2];
                    *(float2*)bfr = *(const float2*)(smem + B_WFRAG
                        + (((gks*8 + wn*4 + nt)*64 + lane*2) << 2));
                    MMA_TF32(acc[nt], a, bfr);
                }
            }
        }

        // epilogue
        int px = wm*16 + (lane >> 2);
        #pragma unroll
        for (int nt = 0; nt < 4; ++nt) {
            int ocb = wn*32 + nt*8 + (lane & 3)*2;
            #pragma unroll
            for (int dd = 0; dd < 4; ++dd) {
                int oc = ocb + (dd & 1);
                int pxx = px + (dd >> 1)*8;
                float wv = acc[nt][dd] + __ldg(b_align + oc);
                g_wact[((b*CC + oc)*HH + h)*WW + pxx] = __expf(fast_sigmoid(wv));
            }
        }
    }
}

// ---------------------------------------------------------------------------
// Kernel C: out = pool3s2(wact*x) / pool3s2(wact), output (4,64,64,64)
// ---------------------------------------------------------------------------
__global__ void k_pool(const float* __restrict__ x, float* __restrict__ out) {
    int idx = blockIdx.x * 256 + threadIdx.x;
    if (idx >= BB*CC*64*64) return;
    int ow = idx & 63;
    int oh = (idx >> 6) & 63;
    int c  = (idx >> 12) & 63;
    int b  = idx >> 18;
    const float* wp = g_wact + ((size_t)b*CC + c)*HWp;
    const float* xp = x      + ((size_t)b*CC + c)*HWp;
    float num = 0.f, den = 0.f;
    int r0 = 2*oh - 1, c0 = 2*ow - 1;
    #pragma unroll
    for (int dr = 0; dr < 3; ++dr) {
        int r = r0 + dr;
        if ((unsigned)r >= HH) continue;
        #pragma unroll
        for (int dc = 0; dc < 3; ++dc) {
            int cl = c0 + dc;
            if ((unsigned)cl >= WW) continue;
            float wv = wp[r*WW + cl];
            num = fmaf(wv, xp[r*WW + cl], num);
            den += wv;
        }
    }
    out[idx] = num / den;
}

// ---------------------------------------------------------------------------
extern "C" void kernel_launch(void* const* d_in, const int* in_sizes, int n_in,
                              void* d_out, int out_size) {
    const float* x       = (const float*)d_in[0];
    const float* w_off   = (const float*)d_in[1];
    const float* b_off   = (const float*)d_in[2];
    const float* w_align = (const float*)d_in[3];
    const float* b_align = (const float*)d_in[4];
    float* out = (float*)d_out;
    (void)in_sizes; (void)n_in; (void)out_size;

    static_assert(B_SMEM <= 227328, "B smem");

    cudaFuncSetAttribute(k_offconv_mma, cudaFuncAttributeMaxDynamicSharedMemorySize, A_SMEM);
    cudaFuncSetAttribute(k_deform_mma,  cudaFuncAttributeMaxDynamicSharedMemorySize, B_SMEM);

    dim3 tg(HWp/32, CC/32, BB);
    k_transpose<<<tg, dim3(32, 8)>>>(x);

    k_offconv_mma<<<148, 512, A_SMEM>>>(w_off, b_off);

    k_deform_mma<<<148, 512, B_SMEM>>>(w_align, b_align);

    k_pool<<<(BB*CC*64*64 + 255)/256, 256>>>(x, out);
}

// round 5
// speedup vs baseline: 3.1954x; 1.0580x over previous
#include <cuda_runtime.h>
#include <cstdint>
#include <math.h>

#define BB 4
#define CC 64
#define HH 128
#define WW 128
#define HWp (HH*WW)
#define OCA 27

// scratch (no allocations allowed)
__device__ float g_xt[BB*HWp*CC];     // x in NHWC
__device__ float g_off[BB*OCA*HWp];   // offset conv out (mask channels = 2*sigmoid)
__device__ float g_wact[BB*CC*HWp];   // exp(sigmoid(align conv)) NCHW

// ============================ helpers =======================================
__device__ __forceinline__ uint32_t s2u(const void* p) {
    uint32_t a;
    asm("{ .reg .u64 t; cvta.to.shared.u64 t, %1; cvt.u32.u64 %0, t; }" : "=r"(a) : "l"(p));
    return a;
}
__device__ __forceinline__ float to_tf32(float x) {
    uint32_t r;
    asm("cvt.rna.tf32.f32 %0, %1;" : "=r"(r) : "f"(x));
    return __uint_as_float(r);
}
#define LDSM_X4(a, addr) \
    asm volatile("ldmatrix.sync.aligned.m8n8.x4.shared.b16 {%0,%1,%2,%3}, [%4];" \
        : "=r"((a)[0]), "=r"((a)[1]), "=r"((a)[2]), "=r"((a)[3]) : "r"(addr))
#define MMA_TF32(d, a, b) \
    asm volatile("mma.sync.aligned.m16n8k8.row.col.f32.tf32.tf32.f32 " \
        "{%0,%1,%2,%3}, {%4,%5,%6,%7}, {%8,%9}, {%0,%1,%2,%3};" \
        : "+f"((d)[0]), "+f"((d)[1]), "+f"((d)[2]), "+f"((d)[3]) \
        : "r"((a)[0]), "r"((a)[1]), "r"((a)[2]), "r"((a)[3]), \
          "r"((b)[0]), "r"((b)[1]))

__device__ __forceinline__ float fast_sigmoid(float v) {
    return __fdividef(1.f, 1.f + __expf(-v));
}

// A-tile swizzle: [128 rows][16 chunks of 16B]; chunk ^= (row&7)
__device__ __forceinline__ uint32_t a_off(int row, int chunk) {
    return (uint32_t)(row*256 + (((chunk ^ (row & 7)) & 15) << 4));
}

__constant__ int cDY[9] = {-1,-1,-1, 0,0,0, 1,1,1};
__constant__ int cDX[9] = {-1, 0, 1,-1,0,1,-1,0,1};

// ---------------------------------------------------------------------------
// Kernel 0: NCHW -> NHWC transpose of x
// ---------------------------------------------------------------------------
__global__ void k_transpose(const float* __restrict__ x) {
    __shared__ float tile[32][33];
    int b  = blockIdx.z;
    int c0 = blockIdx.y * 32;
    int p0 = blockIdx.x * 32;
    int tx = threadIdx.x, ty = threadIdx.y;
    #pragma unroll
    for (int i = ty; i < 32; i += 8)
        tile[i][tx] = x[(b*CC + c0 + i)*HWp + p0 + tx];
    __syncthreads();
    #pragma unroll
    for (int i = ty; i < 32; i += 8)
        g_xt[(b*HWp + p0 + i)*CC + c0 + tx] = tile[tx][i];
}

// ===========================================================================
// Kernel A: 3x3 offset conv 64->27 (pad 32) via tf32 mma.sync, pipelined.
// 16 warps: wm = wid>>1 (16px mtile), wn = wid&1 (2 ntiles = 16 oc).
// Double-buffered ABUF; im2col loads for tap+1 prefetched across MMA(tap).
// ===========================================================================
#define A_WFRAG  0
#define A_ABUF   73728
#define A_SMEM   (A_ABUF + 2*32768)   // 139264

__global__ __launch_bounds__(512, 1)
void k_offconv_mma(const float* __restrict__ w_off, const float* __restrict__ b_off) {
    extern __shared__ char smem[];
    uint32_t sb = s2u(smem);
    int tid = threadIdx.x;
    int wid = tid >> 5, lane = tid & 31;

    // WFRAG: [72 ks][4 nt][lane*2+half] = W[ks*8 + l%4 + half*4][nt*8 + l/4]
    for (int i = tid; i < 72*4*64; i += 512) {
        int half = i & 1, l = (i >> 1) & 31, nt = (i >> 6) & 3, ks = i >> 8;
        int k = ks*8 + (l & 3) + half*4;
        int n = nt*8 + (l >> 2);
        int tap = k >> 6, c = k & 63;
        ((float*)smem)[i] = (n < OCA) ? to_tf32(w_off[(n*CC + c)*9 + tap]) : 0.f;
    }
    __syncthreads();

    int wm = wid >> 1, wn = wid & 1;
    int lrow_in = (lane & 7) + ((lane >> 3) & 1) * 8;
    int g4 = lane >> 4;
    int q16 = tid & 15;
    int pxb = tid >> 4;          // base px (j adds 32)
    const int ntiles = BB*HH;

    for (int tile = blockIdx.x; tile < ntiles; tile += gridDim.x) {
        int h = tile & (HH-1);
        int b = tile >> 7;
        const char* xbb = (const char*)(g_xt + (size_t)b*HWp*CC);

        float acc[2][4];
        #pragma unroll
        for (int nt = 0; nt < 2; ++nt)
            #pragma unroll
            for (int i = 0; i < 4; ++i) acc[nt][i] = 0.f;

        // ---- prologue: fill tap 0 into buf0
        __syncthreads();   // protect ABUF from previous tile's ldmatrix
        {
            int row = h + cDY[0], dxk = cDX[0];
            #pragma unroll
            for (int j = 0; j < 4; ++j) {
                int px = pxb + j*32;
                int col = px + dxk;
                float4 v = make_float4(0.f,0.f,0.f,0.f);
                if ((unsigned)row < HH && (unsigned)col < WW)
                    v = *(const float4*)(xbb + (((size_t)row*WW + col) << 8) + (q16 << 4));
                v.x = to_tf32(v.x); v.y = to_tf32(v.y);
                v.z = to_tf32(v.z); v.w = to_tf32(v.w);
                *(float4*)(smem + A_ABUF + a_off(px, q16)) = v;
            }
        }
        __syncthreads();

        for (int tap = 0; tap < 9; ++tap) {
            int cur = tap & 1, nxt = cur ^ 1;
            bool haven = (tap + 1 < 9);

            // prefetch im2col loads for tap+1 (in regs; no STS yet)
            float4 pv[4];
            if (haven) {
                int row = h + cDY[tap+1], dxk = cDX[tap+1];
                #pragma unroll
                for (int j = 0; j < 4; ++j) {
                    int col = pxb + j*32 + dxk;
                    float4 v = make_float4(0.f,0.f,0.f,0.f);
                    if ((unsigned)row < HH && (unsigned)col < WW)
                        v = *(const float4*)(xbb + (((size_t)row*WW + col) << 8) + (q16 << 4));
                    pv[j] = v;
                }
            }

            // MMA(tap) from buf[cur] — hides the prefetch latency
            uint32_t bufc = sb + A_ABUF + (uint32_t)cur*32768;
            #pragma unroll
            for (int ks = 0; ks < 8; ++ks) {
                int gks = tap*8 + ks;
                int row_a = wm*16 + lrow_in;
                uint32_t a[4];
                LDSM_X4(a, bufc + a_off(row_a, ks*2 + g4));
                #pragma unroll
                for (int nt = 0; nt < 2; ++nt) {
                    uint32_t bfr[2];
                    *(float2*)bfr = *(const float2*)(smem + A_WFRAG
                        + (((gks*4 + wn*2 + nt)*64 + lane*2) << 2));
                    MMA_TF32(acc[nt], a, bfr);
                }
            }

            // consume prefetch -> buf[nxt]
            if (haven) {
                char* bufn = smem + A_ABUF + nxt*32768;
                #pragma unroll
                for (int j = 0; j < 4; ++j) {
                    float4 v = pv[j];
                    v.x = to_tf32(v.x); v.y = to_tf32(v.y);
                    v.z = to_tf32(v.z); v.w = to_tf32(v.w);
                    *(float4*)(bufn + a_off(pxb + j*32, q16)) = v;
                }
            }
            __syncthreads();
        }

        // epilogue: oc = wn*16 + nt*8 + (lane&3)*2 (+1); px = wm*16 + lane/4 (+8)
        #pragma unroll
        for (int nt = 0; nt < 2; ++nt) {
            int ocb = wn*16 + nt*8 + (lane & 3)*2;
            int px  = wm*16 + (lane >> 2);
            #pragma unroll
            for (int dd = 0; dd < 4; ++dd) {
                int oc = ocb + (dd & 1);
                int pxx = px + (dd >> 1)*8;
                if (oc < OCA) {
                    float val = acc[nt][dd] + __ldg(b_off + oc);
                    if (oc >= 18) val = 2.f * fast_sigmoid(val);
                    g_off[((b*OCA + oc)*HH + h)*WW + pxx] = val;
                }
            }
        }
    }
}

// ===========================================================================
// Kernel B: deformable sampling + tf32 mma.sync + exp(sigmoid), pipelined.
// smem: WFRAG [72][8][64] (147456) + 2x ABUF (65536) + 2x meta (8192) = 221184
// 16 warps: wm = wid&7 (16px mtile), wn = wid>>3 (32 oc = 4 ntiles).
// Gather for tap+1 split in 2 halves interleaved with MMA ks 0-3 / 4-7.
// ===========================================================================
#define B_WFRAG  0
#define B_ABUF   147456
#define B_META   (B_ABUF + 2*32768)   // 212992; 2 slots x (2048 w4 + 2048 p4)
#define B_SMEM   (B_META + 2*4096)    // 221184

__device__ __forceinline__ void meta_comp(char* smem, int slot, int tap,
                                          int h, int b, int tid) {
    if (tid < 128) {
        int px = tid;
        const float* ob = g_off + (size_t)b*OCA*HWp + (size_t)h*WW + px;
        float dy = ob[(2*tap    )*HWp];
        float dx = ob[(2*tap + 1)*HWp];
        float m  = ob[(18 + tap )*HWp];
        float Y = (float)(h  + cDY[tap]) + dy;
        float X = (float)(px + cDX[tap]) + dx;
        float yf = floorf(Y), xf = floorf(X);
        int y0 = (int)yf, x0 = (int)xf;
        float fy = Y - yf, fx = X - xf;
        bool y0v = ((unsigned)y0     < HH);
        bool y1v = ((unsigned)(y0+1) < HH);
        bool x0v = ((unsigned)x0     < WW);
        bool x1v = ((unsigned)(x0+1) < WW);
        float4 w4;
        w4.x = (1.f-fy)*(1.f-fx) * m * (y0v && x0v);
        w4.y = (1.f-fy)*fx       * m * (y0v && x1v);
        w4.z = fy*(1.f-fx)       * m * (y1v && x0v);
        w4.w = fy*fx             * m * (y1v && x1v);
        int yc0 = min(max(y0, 0), HH-1), yc1 = min(max(y0+1, 0), HH-1);
        int xc0 = min(max(x0, 0), WW-1), xc1 = min(max(x0+1, 0), WW-1);
        int4 p4;
        p4.x = (yc0*WW + xc0) << 8;
        p4.y = (yc0*WW + xc1) << 8;
        p4.z = (yc1*WW + xc0) << 8;
        p4.w = (yc1*WW + xc1) << 8;
        ((float4*)(smem + B_META + slot*4096))[px] = w4;
        ((int4*)  (smem + B_META + slot*4096 + 2048))[px] = p4;
    }
}

__global__ __launch_bounds__(512, 1)
void k_deform_mma(const float* __restrict__ w_align, const float* __restrict__ b_align) {
    extern __shared__ char smem[];
    uint32_t sb = s2u(smem);
    int tid = threadIdx.x;
    int wid = tid >> 5, lane = tid & 31;

    for (int i = tid; i < 72*8*64; i += 512) {
        int half = i & 1, l = (i >> 1) & 31, nt = (i >> 6) & 7, ks = i >> 9;
        int k = ks*8 + (l & 3) + half*4;
        int n = nt*8 + (l >> 2);
        int tap = k >> 6, c = k & 63;
        ((float*)smem)[i] = to_tf32(w_align[(n*CC + c)*9 + tap]);
    }
    __syncthreads();

    int wm = wid & 7, wn = wid >> 3;
    int lrow_in = (lane & 7) + ((lane >> 3) & 1) * 8;
    int g4 = lane >> 4;
    int q16 = tid & 15;
    int qo  = q16 << 4;
    int pxb = tid >> 4;
    const int ntiles = BB*HH;

    for (int tile = blockIdx.x; tile < ntiles; tile += gridDim.x) {
        int h = tile & (HH-1);
        int b = tile >> 7;
        const char* xbb = (const char*)(g_xt + (size_t)b*HWp*CC);

        float acc[4][4];
        #pragma unroll
        for (int nt = 0; nt < 4; ++nt)
            #pragma unroll
            for (int i = 0; i < 4; ++i) acc[nt][i] = 0.f;

        // ---- prologue: meta(0)->slot0, meta(1)->slot1; gather(0)->buf0
        __syncthreads();   // protect ABUF/meta from previous tile's reads
        meta_comp(smem, 0, 0, h, b, tid);
        meta_comp(smem, 1, 1, h, b, tid);
        __syncthreads();
        {
            const float4* mW = (const float4*)(smem + B_META);
            const int4*   mP = (const int4*)  (smem + B_META + 2048);
            #pragma unroll
            for (int j = 0; j < 4; ++j) {
                int px = pxb + j*32;
                float4 w4 = mW[px];
                int4   p4 = mP[px];
                float4 c00 = *(const float4*)(xbb + p4.x + qo);
                float4 c01 = *(const float4*)(xbb + p4.y + qo);
                float4 c10 = *(const float4*)(xbb + p4.z + qo);
                float4 c11 = *(const float4*)(xbb + p4.w + qo);
                float4 v;
                v.x = fmaf(w4.x,c00.x, fmaf(w4.y,c01.x, fmaf(w4.z,c10.x, w4.w*c11.x)));
                v.y = fmaf(w4.x,c00.y, fmaf(w4.y,c01.y, fmaf(w4.z,c10.y, w4.w*c11.y)));
                v.z = fmaf(w4.x,c00.z, fmaf(w4.y,c01.z, fmaf(w4.z,c10.z, w4.w*c11.z)));
                v.w = fmaf(w4.x,c00.w, fmaf(w4.y,c01.w, fmaf(w4.z,c10.w, w4.w*c11.w)));
                v.x = to_tf32(v.x); v.y = to_tf32(v.y);
                v.z = to_tf32(v.z); v.w = to_tf32(v.w);
                *(float4*)(smem + B_ABUF + a_off(px, q16)) = v;
            }
        }
        __syncthreads();

        for (int tap = 0; tap < 9; ++tap) {
            int cur = tap & 1, nxt = cur ^ 1;
            bool haven = (tap + 1 < 9);
            uint32_t bufc = sb + B_ABUF + (uint32_t)cur*32768;
            char*    bufn = smem + B_ABUF + nxt*32768;
            const float4* mW = (const float4*)(smem + B_META + nxt*4096);
            const int4*   mP = (const int4*)  (smem + B_META + nxt*4096 + 2048);

            #pragma unroll
            for (int half = 0; half < 2; ++half) {
                // load gather corners for 2 j's of tap+1
                float4 C[2][4]; float4 w4_[2]; int pxs[2];
                if (haven) {
                    #pragma unroll
                    for (int jj = 0; jj < 2; ++jj) {
                        int px = pxb + (half*2 + jj)*32;
                        pxs[jj] = px;
                        w4_[jj] = mW[px];
                        int4 p4 = mP[px];
                        C[jj][0] = *(const float4*)(xbb + p4.x + qo);
                        C[jj][1] = *(const float4*)(xbb + p4.y + qo);
                        C[jj][2] = *(const float4*)(xbb + p4.z + qo);
                        C[jj][3] = *(const float4*)(xbb + p4.w + qo);
                    }
                }
                // MMA ks half*4 .. half*4+3 (hides the loads above)
                #pragma unroll
                for (int k4 = 0; k4 < 4; ++k4) {
                    int ks = half*4 + k4;
                    int gks = tap*8 + ks;
                    int row_a = wm*16 + lrow_in;
                    uint32_t a[4];
                    LDSM_X4(a, bufc + a_off(row_a, ks*2 + g4));
                    #pragma unroll
                    for (int nt = 0; nt < 4; ++nt) {
                        uint32_t bfr[2];
                        *(float2*)bfr = *(const float2*)(smem + B_WFRAG
                            + (((gks*8 + wn*4 + nt)*64 + lane*2) << 2));
                        MMA_TF32(acc[nt], a, bfr);
                    }
                }
                // consume -> buf[nxt]
                if (haven) {
                    #pragma unroll
                    for (int jj = 0; jj < 2; ++jj) {
                        float4 w4 = w4_[jj];
                        float4 v;
                        v.x = fmaf(w4.x,C[jj][0].x, fmaf(w4.y,C[jj][1].x, fmaf(w4.z,C[jj][2].x, w4.w*C[jj][3].x)));
                        v.y = fmaf(w4.x,C[jj][0].y, fmaf(w4.y,C[jj][1].y, fmaf(w4.z,C[jj][2].y, w4.w*C[jj][3].y)));
                        v.z = fmaf(w4.x,C[jj][0].z, fmaf(w4.y,C[jj][1].z, fmaf(w4.z,C[jj][2].z, w4.w*C[jj][3].z)));
                        v.w = fmaf(w4.x,C[jj][0].w, fmaf(w4.y,C[jj][1].w, fmaf(w4.z,C[jj][2].w, w4.w*C[jj][3].w)));
                        v.x = to_tf32(v.x); v.y = to_tf32(v.y);
                        v.z = to_tf32(v.z); v.w = to_tf32(v.w);
                        *(float4*)(bufn + a_off(pxs[jj], q16)) = v;
                    }
                }
            }
            // meta for tap+2 -> slot cur
            if (tap + 2 < 9) meta_comp(smem, cur, tap + 2, h, b, tid);
            __syncthreads();
        }

        // epilogue
        int px = wm*16 + (lane >> 2);
        #pragma unroll
        for (int nt = 0; nt < 4; ++nt) {
            int ocb = wn*32 + nt*8 + (lane & 3)*2;
            #pragma unroll
            for (int dd = 0; dd < 4; ++dd) {
                int oc = ocb + (dd & 1);
                int pxx = px + (dd >> 1)*8;
                float wv = acc[nt][dd] + __ldg(b_align + oc);
                g_wact[((b*CC + oc)*HH + h)*WW + pxx] = __expf(fast_sigmoid(wv));
            }
        }
    }
}

// ---------------------------------------------------------------------------
// Kernel C: out = pool3s2(wact*x) / pool3s2(wact), output (4,64,64,64)
// ---------------------------------------------------------------------------
__global__ void k_pool(const float* __restrict__ x, float* __restrict__ out) {
    int idx = blockIdx.x * 256 + threadIdx.x;
    if (idx >= BB*CC*64*64) return;
    int ow = idx & 63;
    int oh = (idx >> 6) & 63;
    int c  = (idx >> 12) & 63;
    int b  = idx >> 18;
    const float* wp = g_wact + ((size_t)b*CC + c)*HWp;
    const float* xp = x      + ((size_t)b*CC + c)*HWp;
    float num = 0.f, den = 0.f;
    int r0 = 2*oh - 1, c0 = 2*ow - 1;
    #pragma unroll
    for (int dr = 0; dr < 3; ++dr) {
        int r = r0 + dr;
        if ((unsigned)r >= HH) continue;
        #pragma unroll
        for (int dc = 0; dc < 3; ++dc) {
            int cl = c0 + dc;
            if ((unsigned)cl >= WW) continue;
            float wv = wp[r*WW + cl];
            num = fmaf(wv, xp[r*WW + cl], num);
            den += wv;
        }
    }
    out[idx] = num / den;
}

// ---------------------------------------------------------------------------
extern "C" void kernel_launch(void* const* d_in, const int* in_sizes, int n_in,
                              void* d_out, int out_size) {
    const float* x       = (const float*)d_in[0];
    const float* w_off   = (const float*)d_in[1];
    const float* b_off   = (const float*)d_in[2];
    const float* w_align = (const float*)d_in[3];
    const float* b_align = (const float*)d_in[4];
    float* out = (float*)d_out;
    (void)in_sizes; (void)n_in; (void)out_size;

    static_assert(B_SMEM <= 227328, "B smem");

    cudaFuncSetAttribute(k_offconv_mma, cudaFuncAttributeMaxDynamicSharedMemorySize, A_SMEM);
    cudaFuncSetAttribute(k_deform_mma,  cudaFuncAttributeMaxDynamicSharedMemorySize, B_SMEM);

    dim3 tg(HWp/32, CC/32, BB);
    k_transpose<<<tg, dim3(32, 8)>>>(x);

    k_offconv_mma<<<148, 512, A_SMEM>>>(w_off, b_off);

    k_deform_mma<<<148, 512, B_SMEM>>>(w_align, b_align);

    k_pool<<<(BB*CC*64*64 + 255)/256, 256>>>(x, out);
}

// round 6
// speedup vs baseline: 4.6626x; 1.4592x over previous
#include <cuda_runtime.h>
#include <cuda_fp16.h>
#include <cstdint>
#include <math.h>

#define BB 4
#define CC 64
#define HH 128
#define WW 128
#define HWp (HH*WW)
#define OCA 27

// scratch (no allocations allowed)
__device__ __half g_xt16[BB*HWp*CC];  // x in NHWC, fp16 (128B per pixel)
__device__ float  g_off[BB*OCA*HWp];  // offset conv out (mask channels = 2*sigmoid)
__device__ float  g_wact[BB*CC*HWp];  // exp(sigmoid(align conv)) NCHW

// ============================ helpers =======================================
__device__ __forceinline__ uint32_t s2u(const void* p) {
    uint32_t a;
    asm("{ .reg .u64 t; cvta.to.shared.u64 t, %1; cvt.u32.u64 %0, t; }" : "=r"(a) : "l"(p));
    return a;
}
#define LDSM_X4(a, addr) \
    asm volatile("ldmatrix.sync.aligned.m8n8.x4.shared.b16 {%0,%1,%2,%3}, [%4];" \
        : "=r"((a)[0]), "=r"((a)[1]), "=r"((a)[2]), "=r"((a)[3]) : "r"(addr))
#define MMA_F16(d, a, b) \
    asm volatile("mma.sync.aligned.m16n8k16.row.col.f32.f16.f16.f32 " \
        "{%0,%1,%2,%3}, {%4,%5,%6,%7}, {%8,%9}, {%0,%1,%2,%3};" \
        : "+f"((d)[0]), "+f"((d)[1]), "+f"((d)[2]), "+f"((d)[3]) \
        : "r"((a)[0]), "r"((a)[1]), "r"((a)[2]), "r"((a)[3]), \
          "r"((b)[0]), "r"((b)[1]))

__device__ __forceinline__ float fast_sigmoid(float v) {
    return __fdividef(1.f, 1.f + __expf(-v));
}

// fp16 A-tile: [128 rows][8 chunks of 16B]; chunk ^= (row&7)
__device__ __forceinline__ uint32_t a16_off(int row, int chunk) {
    return (uint32_t)(row*128 + (((chunk ^ (row & 7)) & 7) << 4));
}

__constant__ int cDY[9] = {-1,-1,-1, 0,0,0, 1,1,1};
__constant__ int cDX[9] = {-1, 0, 1,-1,0,1,-1,0,1};

// ---------------------------------------------------------------------------
// Kernel 0: NCHW fp32 -> NHWC fp16
// ---------------------------------------------------------------------------
__global__ void k_transpose(const float* __restrict__ x) {
    __shared__ float tile[32][33];
    int b  = blockIdx.z;
    int c0 = blockIdx.y * 32;
    int p0 = blockIdx.x * 32;
    int tx = threadIdx.x, ty = threadIdx.y;
    #pragma unroll
    for (int i = ty; i < 32; i += 8)
        tile[i][tx] = x[(b*CC + c0 + i)*HWp + p0 + tx];
    __syncthreads();
    #pragma unroll
    for (int i = ty; i < 32; i += 8)
        g_xt16[(b*HWp + p0 + i)*CC + c0 + tx] = __float2half_rn(tile[tx][i]);
}

// ===========================================================================
// Kernel A: 3x3 offset conv 64->27 (pad 32) via fp16 m16n8k16, pipelined.
// 16 warps: wm = wid>>1 (16px), wn = wid&1 (16 oc). 2 CTAs/SM.
// ===========================================================================
#define A_WFRAG  0
#define A_ABUF   36864                 // 36*4*32*8
#define A_SMEM   (A_ABUF + 2*16384)   // 69632

__global__ __launch_bounds__(512, 2)
void k_offconv_mma(const float* __restrict__ w_off, const float* __restrict__ b_off) {
    extern __shared__ char smem[];
    uint32_t sb = s2u(smem);
    int tid = threadIdx.x;
    int wid = tid >> 5, lane = tid & 31;

    // WFRAG: [36 gks][4 ntg][32 lane] x 4 halves (k0,k0+1,k0+8,k0+9 ; n)
    for (int i = tid; i < 36*4*32; i += 512) {
        int l = i & 31, ntg = (i >> 5) & 3, gks = i >> 7;
        int k0 = gks*16 + (l & 3)*2;
        int n  = ntg*8 + (l >> 2);
        __half h[4];
        #pragma unroll
        for (int j = 0; j < 4; ++j) {
            int k = k0 + (j & 1) + (j >> 1)*8;
            int tap = k >> 6, c = k & 63;
            h[j] = (n < OCA) ? __float2half_rn(w_off[(n*CC + c)*9 + tap])
                             : __half(0.f);
        }
        *(uint2*)(smem + (size_t)i*8) = *(uint2*)h;
    }
    __syncthreads();

    int wm = wid >> 1, wn = wid & 1;
    int lrow_in = (lane & 7) + (lane & 8);
    int g2 = lane >> 4;
    int ch8 = tid & 7;            // 8-channel group
    int pxh = tid >> 3;           // 0..63, +64 for pass 1
    const int ntiles = BB*HH;

    for (int tile = blockIdx.x; tile < ntiles; tile += gridDim.x) {
        int h = tile & (HH-1);
        int b = tile >> 7;
        const char* xbb = (const char*)(g_xt16 + (size_t)b*HWp*CC);

        float acc[2][4];
        #pragma unroll
        for (int nt = 0; nt < 2; ++nt)
            #pragma unroll
            for (int i = 0; i < 4; ++i) acc[nt][i] = 0.f;

        __syncthreads();
        {   // prologue: tap 0 -> buf0
            int row = h + cDY[0], dxk = cDX[0];
            #pragma unroll
            for (int j = 0; j < 2; ++j) {
                int px = pxh + j*64;
                int col = px + dxk;
                uint4 v = make_uint4(0,0,0,0);
                if ((unsigned)row < HH && (unsigned)col < WW)
                    v = *(const uint4*)(xbb + (((size_t)row*WW + col) << 7) + (ch8 << 4));
                *(uint4*)(smem + A_ABUF + a16_off(px, ch8)) = v;
            }
        }
        __syncthreads();

        for (int tap = 0; tap < 9; ++tap) {
            int cur = tap & 1, nxt = cur ^ 1;
            bool haven = (tap + 1 < 9);

            uint4 pv[2];
            if (haven) {
                int row = h + cDY[tap+1], dxk = cDX[tap+1];
                #pragma unroll
                for (int j = 0; j < 2; ++j) {
                    int col = pxh + j*64 + dxk;
                    uint4 v = make_uint4(0,0,0,0);
                    if ((unsigned)row < HH && (unsigned)col < WW)
                        v = *(const uint4*)(xbb + (((size_t)row*WW + col) << 7) + (ch8 << 4));
                    pv[j] = v;
                }
            }

            uint32_t bufc = sb + A_ABUF + (uint32_t)cur*16384;
            #pragma unroll
            for (int ks = 0; ks < 4; ++ks) {
                int gks = tap*4 + ks;
                uint32_t a[4];
                LDSM_X4(a, bufc + a16_off(wm*16 + lrow_in, ks*2 + g2));
                #pragma unroll
                for (int nt = 0; nt < 2; ++nt) {
                    uint32_t bfr[2];
                    *(uint2*)bfr = *(const uint2*)(smem + A_WFRAG
                        + (((size_t)(gks*4 + wn*2 + nt)*32 + lane) << 3));
                    MMA_F16(acc[nt], a, bfr);
                }
            }

            if (haven) {
                char* bufn = smem + A_ABUF + nxt*16384;
                #pragma unroll
                for (int j = 0; j < 2; ++j)
                    *(uint4*)(bufn + a16_off(pxh + j*64, ch8)) = pv[j];
            }
            __syncthreads();
        }

        #pragma unroll
        for (int nt = 0; nt < 2; ++nt) {
            int ocb = wn*16 + nt*8 + (lane & 3)*2;
            int px  = wm*16 + (lane >> 2);
            #pragma unroll
            for (int dd = 0; dd < 4; ++dd) {
                int oc = ocb + (dd & 1);
                int pxx = px + (dd >> 1)*8;
                if (oc < OCA) {
                    float val = acc[nt][dd] + __ldg(b_off + oc);
                    if (oc >= 18) val = 2.f * fast_sigmoid(val);
                    g_off[((b*OCA + oc)*HH + h)*WW + pxx] = val;
                }
            }
        }
    }
}

// ===========================================================================
// Kernel B: deformable sampling + fp16 m16n8k16 + exp(sigmoid), pipelined.
// smem: WFRAG 73728 + 2x ABUF 32768 + 2x meta 8192 = 114688.
// 16 warps: wm = wid&7 (16px), wn = wid>>3 (32 oc).
// ===========================================================================
#define B_WFRAG  0
#define B_ABUF   73728
#define B_META   (B_ABUF + 2*16384)   // 106496
#define B_SMEM   (B_META + 2*4096)    // 114688

__device__ __forceinline__ void meta_comp(char* smem, int slot, int tap,
                                          int h, int b, int tid) {
    if (tid < 128) {
        int px = tid;
        const float* ob = g_off + (size_t)b*OCA*HWp + (size_t)h*WW + px;
        float dy = ob[(2*tap    )*HWp];
        float dx = ob[(2*tap + 1)*HWp];
        float m  = ob[(18 + tap )*HWp];
        float Y = (float)(h  + cDY[tap]) + dy;
        float X = (float)(px + cDX[tap]) + dx;
        float yf = floorf(Y), xf = floorf(X);
        int y0 = (int)yf, x0 = (int)xf;
        float fy = Y - yf, fx = X - xf;
        bool y0v = ((unsigned)y0     < HH);
        bool y1v = ((unsigned)(y0+1) < HH);
        bool x0v = ((unsigned)x0     < WW);
        bool x1v = ((unsigned)(x0+1) < WW);
        float4 w4;
        w4.x = (1.f-fy)*(1.f-fx) * m * (y0v && x0v);
        w4.y = (1.f-fy)*fx       * m * (y0v && x1v);
        w4.z = fy*(1.f-fx)       * m * (y1v && x0v);
        w4.w = fy*fx             * m * (y1v && x1v);
        int yc0 = min(max(y0, 0), HH-1), yc1 = min(max(y0+1, 0), HH-1);
        int xc0 = min(max(x0, 0), WW-1), xc1 = min(max(x0+1, 0), WW-1);
        int4 p4;
        p4.x = (yc0*WW + xc0) << 7;   // fp16: 128B per pixel
        p4.y = (yc0*WW + xc1) << 7;
        p4.z = (yc1*WW + xc0) << 7;
        p4.w = (yc1*WW + xc1) << 7;
        ((float4*)(smem + B_META + slot*4096))[px] = w4;
        ((int4*)  (smem + B_META + slot*4096 + 2048))[px] = p4;
    }
}

// bilinear combine of 4 fp16 corner vectors (8 ch) -> fp16 result
__device__ __forceinline__ uint4 bilerp8(uint4 c00, uint4 c01, uint4 c10, uint4 c11,
                                         float4 w4) {
    uint4 out;
    uint32_t* pc00 = (uint32_t*)&c00;
    uint32_t* pc01 = (uint32_t*)&c01;
    uint32_t* pc10 = (uint32_t*)&c10;
    uint32_t* pc11 = (uint32_t*)&c11;
    uint32_t* po   = (uint32_t*)&out;
    #pragma unroll
    for (int hp = 0; hp < 4; ++hp) {
        float2 f00 = __half22float2(*(const __half2*)&pc00[hp]);
        float2 f01 = __half22float2(*(const __half2*)&pc01[hp]);
        float2 f10 = __half22float2(*(const __half2*)&pc10[hp]);
        float2 f11 = __half22float2(*(const __half2*)&pc11[hp]);
        float vx = fmaf(w4.x,f00.x, fmaf(w4.y,f01.x, fmaf(w4.z,f10.x, w4.w*f11.x)));
        float vy = fmaf(w4.x,f00.y, fmaf(w4.y,f01.y, fmaf(w4.z,f10.y, w4.w*f11.y)));
        __half2 hv = __floats2half2_rn(vx, vy);
        po[hp] = *(const uint32_t*)&hv;
    }
    return out;
}

__global__ __launch_bounds__(512, 1)
void k_deform_mma(const float* __restrict__ w_align, const float* __restrict__ b_align) {
    extern __shared__ char smem[];
    uint32_t sb = s2u(smem);
    int tid = threadIdx.x;
    int wid = tid >> 5, lane = tid & 31;

    // WFRAG: [36 gks][8 ntg][32 lane] x 4 halves
    for (int i = tid; i < 36*8*32; i += 512) {
        int l = i & 31, ntg = (i >> 5) & 7, gks = i >> 8;
        int k0 = gks*16 + (l & 3)*2;
        int n  = ntg*8 + (l >> 2);
        __half h[4];
        #pragma unroll
        for (int j = 0; j < 4; ++j) {
            int k = k0 + (j & 1) + (j >> 1)*8;
            int tap = k >> 6, c = k & 63;
            h[j] = __float2half_rn(w_align[(n*CC + c)*9 + tap]);
        }
        *(uint2*)(smem + (size_t)i*8) = *(uint2*)h;
    }
    __syncthreads();

    int wm = wid & 7, wn = wid >> 3;
    int lrow_in = (lane & 7) + (lane & 8);
    int g2 = lane >> 4;
    int ch8 = tid & 7;
    int pxh = tid >> 3;           // 0..63
    const int ntiles = BB*HH;

    for (int tile = blockIdx.x; tile < ntiles; tile += gridDim.x) {
        int h = tile & (HH-1);
        int b = tile >> 7;
        const char* xbb = (const char*)(g_xt16 + (size_t)b*HWp*CC);

        float acc[4][4];
        #pragma unroll
        for (int nt = 0; nt < 4; ++nt)
            #pragma unroll
            for (int i = 0; i < 4; ++i) acc[nt][i] = 0.f;

        __syncthreads();
        meta_comp(smem, 0, 0, h, b, tid);
        meta_comp(smem, 1, 1, h, b, tid);
        __syncthreads();
        {   // prologue: gather tap0 -> buf0
            const float4* mW = (const float4*)(smem + B_META);
            const int4*   mP = (const int4*)  (smem + B_META + 2048);
            #pragma unroll
            for (int j = 0; j < 2; ++j) {
                int px = pxh + j*64;
                float4 w4 = mW[px];
                int4   p4 = mP[px];
                int qo = ch8 << 4;
                uint4 c00 = *(const uint4*)(xbb + p4.x + qo);
                uint4 c01 = *(const uint4*)(xbb + p4.y + qo);
                uint4 c10 = *(const uint4*)(xbb + p4.z + qo);
                uint4 c11 = *(const uint4*)(xbb + p4.w + qo);
                *(uint4*)(smem + B_ABUF + a16_off(px, ch8)) = bilerp8(c00,c01,c10,c11,w4);
            }
        }
        __syncthreads();

        for (int tap = 0; tap < 9; ++tap) {
            int cur = tap & 1, nxt = cur ^ 1;
            bool haven = (tap + 1 < 9);
            uint32_t bufc = sb + B_ABUF + (uint32_t)cur*16384;
            char*    bufn = smem + B_ABUF + nxt*16384;
            const float4* mW = (const float4*)(smem + B_META + nxt*4096);
            const int4*   mP = (const int4*)  (smem + B_META + nxt*4096 + 2048);

            #pragma unroll
            for (int half = 0; half < 2; ++half) {
                // gather pass 'half' of tap+1
                uint4 C[4]; float4 w4; int pxs = pxh + half*64;
                if (haven) {
                    w4 = mW[pxs];
                    int4 p4 = mP[pxs];
                    int qo = ch8 << 4;
                    C[0] = *(const uint4*)(xbb + p4.x + qo);
                    C[1] = *(const uint4*)(xbb + p4.y + qo);
                    C[2] = *(const uint4*)(xbb + p4.z + qo);
                    C[3] = *(const uint4*)(xbb + p4.w + qo);
                }
                // MMA ks half*2 .. half*2+1 (hides the loads)
                #pragma unroll
                for (int k2 = 0; k2 < 2; ++k2) {
                    int ks = half*2 + k2;
                    int gks = tap*4 + ks;
                    uint32_t a[4];
                    LDSM_X4(a, bufc + a16_off(wm*16 + lrow_in, ks*2 + g2));
                    #pragma unroll
                    for (int nt = 0; nt < 4; ++nt) {
                        uint32_t bfr[2];
                        *(uint2*)bfr = *(const uint2*)(smem + B_WFRAG
                            + (((size_t)(gks*8 + wn*4 + nt)*32 + lane) << 3));
                        MMA_F16(acc[nt], a, bfr);
                    }
                }
                if (haven)
                    *(uint4*)(bufn + a16_off(pxs, ch8)) = bilerp8(C[0],C[1],C[2],C[3],w4);
            }
            if (tap + 2 < 9) meta_comp(smem, cur, tap + 2, h, b, tid);
            __syncthreads();
        }

        // epilogue
        int px = wm*16 + (lane >> 2);
        #pragma unroll
        for (int nt = 0; nt < 4; ++nt) {
            int ocb = wn*32 + nt*8 + (lane & 3)*2;
            #pragma unroll
            for (int dd = 0; dd < 4; ++dd) {
                int oc = ocb + (dd & 1);
                int pxx = px + (dd >> 1)*8;
                float wv = acc[nt][dd] + __ldg(b_align + oc);
                g_wact[((b*CC + oc)*HH + h)*WW + pxx] = __expf(fast_sigmoid(wv));
            }
        }
    }
}

// ---------------------------------------------------------------------------
// Kernel C: out = pool3s2(wact*x) / pool3s2(wact), output (4,64,64,64)
// ---------------------------------------------------------------------------
__global__ void k_pool(const float* __restrict__ x, float* __restrict__ out) {
    int idx = blockIdx.x * 256 + threadIdx.x;
    if (idx >= BB*CC*64*64) return;
    int ow = idx & 63;
    int oh = (idx >> 6) & 63;
    int c  = (idx >> 12) & 63;
    int b  = idx >> 18;
    const float* wp = g_wact + ((size_t)b*CC + c)*HWp;
    const float* xp = x      + ((size_t)b*CC + c)*HWp;
    float num = 0.f, den = 0.f;
    int r0 = 2*oh - 1, c0 = 2*ow - 1;
    #pragma unroll
    for (int dr = 0; dr < 3; ++dr) {
        int r = r0 + dr;
        if ((unsigned)r >= HH) continue;
        #pragma unroll
        for (int dc = 0; dc < 3; ++dc) {
            int cl = c0 + dc;
            if ((unsigned)cl >= WW) continue;
            float wv = wp[r*WW + cl];
            num = fmaf(wv, xp[r*WW + cl], num);
            den += wv;
        }
    }
    out[idx] = num / den;
}

// ---------------------------------------------------------------------------
extern "C" void kernel_launch(void* const* d_in, const int* in_sizes, int n_in,
                              void* d_out, int out_size) {
    const float* x       = (const float*)d_in[0];
    const float* w_off   = (const float*)d_in[1];
    const float* b_off   = (const float*)d_in[2];
    const float* w_align = (const float*)d_in[3];
    const float* b_align = (const float*)d_in[4];
    float* out = (float*)d_out;
    (void)in_sizes; (void)n_in; (void)out_size;

    static_assert(A_SMEM <= 113664, "A smem (2 CTAs)");
    static_assert(B_SMEM <= 227328, "B smem");

    cudaFuncSetAttribute(k_offconv_mma, cudaFuncAttributeMaxDynamicSharedMemorySize, A_SMEM);
    cudaFuncSetAttribute(k_deform_mma,  cudaFuncAttributeMaxDynamicSharedMemorySize, B_SMEM);

    dim3 tg(HWp/32, CC/32, BB);
    k_transpose<<<tg, dim3(32, 8)>>>(x);

    k_offconv_mma<<<296, 512, A_SMEM>>>(w_off, b_off);

    k_deform_mma<<<148, 512, B_SMEM>>>(w_align, b_align);

    k_pool<<<(BB*CC*64*64 + 255)/256, 256>>>(x, out);
}